// round 1
// baseline (speedup 1.0000x reference)
#include <cuda_runtime.h>

#define N_NODES 100000
#define N_EDGES 3200000
#define NFEAT   128
#define F1      16
#define F2      4
#define F3      2
#define NC      8

// ---------------- scratch (device globals; no allocation allowed) ----------
__device__ int g_is64;
__device__ __align__(16) int   g_src[N_EDGES];
__device__ __align__(16) int   g_dst[N_EDGES];
__device__ __align__(16) int   g_cnt[N_NODES];
__device__ __align__(16) float g_dinv[N_NODES];
__device__ __align__(16) float g_xw1 [N_NODES * F1];
__device__ __align__(16) float g_agg1[N_NODES * F1];
__device__ __align__(16) float g_xw2 [N_NODES * F2];
__device__ __align__(16) float g_agg2[N_NODES * F2];
__device__ __align__(16) float g_xw3 [N_NODES * F3];
__device__ __align__(16) float g_agg3[N_NODES * F3];

// ---------------- helpers ---------------------------------------------------
__device__ __forceinline__ void red_v4(float* p, float x, float y, float z, float w) {
    asm volatile("red.global.add.v4.f32 [%0], {%1, %2, %3, %4};"
                 :: "l"(p), "f"(x), "f"(y), "f"(z), "f"(w) : "memory");
}
__device__ __forceinline__ void red_v2(float* p, float x, float y) {
    asm volatile("red.global.add.v2.f32 [%0], {%1, %2};"
                 :: "l"(p), "f"(x), "f"(y) : "memory");
}

// ---------------- K0: detect int64 vs int32 edge_index ---------------------
// int64 little-endian with values < 100000 => every odd 32-bit word is 0.
__global__ void k_detect(const unsigned int* __restrict__ w) {
    __shared__ unsigned int s;
    if (threadIdx.x == 0) s = 0u;
    __syncthreads();
    unsigned int nz = 0;
    for (int i = threadIdx.x; i < 2048; i += blockDim.x) nz |= w[2 * i + 1];
    atomicOr(&s, nz);
    __syncthreads();
    if (threadIdx.x == 0) g_is64 = (s == 0u) ? 1 : 0;
}

// ---------------- K1: zero accumulators ------------------------------------
__global__ void k_zero() {
    int i = blockIdx.x * blockDim.x + threadIdx.x;
    int stride = gridDim.x * blockDim.x;
    for (int j = i; j < N_NODES * F1; j += stride) g_agg1[j] = 0.0f;
    for (int j = i; j < N_NODES * F2; j += stride) g_agg2[j] = 0.0f;
    for (int j = i; j < N_NODES * F3; j += stride) g_agg3[j] = 0.0f;
    for (int j = i; j < N_NODES;      j += stride) g_cnt[j]  = 0;
}

// ---------------- K2: convert edges to int32 + degree count ----------------
__global__ void k_edges(const int* __restrict__ ei) {
    int e = blockIdx.x * blockDim.x + threadIdx.x;
    if (e >= N_EDGES) return;
    int s, d;
    if (g_is64) { s = ei[2 * e]; d = ei[2 * (N_EDGES + e)]; }
    else        { s = ei[e];     d = ei[N_EDGES + e]; }
    g_src[e] = s;
    g_dst[e] = d;
    atomicAdd(&g_cnt[d], 1);
}

// ---------------- K3: dinv = rsqrt(deg) (deg includes self-loop) -----------
__global__ void k_dinv() {
    int n = blockIdx.x * blockDim.x + threadIdx.x;
    if (n >= N_NODES) return;
    g_dinv[n] = rsqrtf((float)(g_cnt[n] + 1));
}

// ---------------- K4: xw1 = h @ W1   (100k x 128 @ 128 x 16) ---------------
__global__ void k_xw1(const float* __restrict__ h, const float* __restrict__ W1) {
    __shared__ float sW[NFEAT * F1];   // 8 KB
    for (int i = threadIdx.x; i < NFEAT * F1; i += blockDim.x) sW[i] = W1[i];
    __syncthreads();
    int n = blockIdx.x * blockDim.x + threadIdx.x;
    if (n >= N_NODES) return;

    float acc[F1];
#pragma unroll
    for (int f = 0; f < F1; f++) acc[f] = 0.0f;

    const float4* h4 = reinterpret_cast<const float4*>(h + (size_t)n * NFEAT);
#pragma unroll 4
    for (int k4 = 0; k4 < NFEAT / 4; k4++) {
        float4 hv = h4[k4];
        const float* w = &sW[(k4 * 4) * F1];
#pragma unroll
        for (int f = 0; f < F1; f++) {
            float a = acc[f];
            a = fmaf(hv.x, w[f],          a);
            a = fmaf(hv.y, w[F1 + f],     a);
            a = fmaf(hv.z, w[2 * F1 + f], a);
            a = fmaf(hv.w, w[3 * F1 + f], a);
            acc[f] = a;
        }
    }
    float4* o = reinterpret_cast<float4*>(g_xw1 + n * F1);
#pragma unroll
    for (int q = 0; q < F1 / 4; q++)
        o[q] = make_float4(acc[4 * q], acc[4 * q + 1], acc[4 * q + 2], acc[4 * q + 3]);
}

// ---------------- K5: scatter layer-1 (4 threads / edge, v4 red) -----------
__global__ void k_scat1() {
    int idx = blockIdx.x * blockDim.x + threadIdx.x;
    if (idx >= N_EDGES * 4) return;
    int e = idx >> 2;
    int c = idx & 3;
    int s = g_src[e], d = g_dst[e];
    float nrm = g_dinv[s] * g_dinv[d];
    float4 v = *reinterpret_cast<const float4*>(g_xw1 + s * F1 + c * 4);
    red_v4(g_agg1 + d * F1 + c * 4, v.x * nrm, v.y * nrm, v.z * nrm, v.w * nrm);
}

// ---------------- K6: h1 = tanh(agg1 + self + b1); xw2 = h1 @ W2 -----------
__global__ void k_l2(const float* __restrict__ b1, const float* __restrict__ W2) {
    __shared__ float sW2[F1 * F2];  // 64
    __shared__ float sb1[F1];
    for (int i = threadIdx.x; i < F1 * F2; i += blockDim.x) sW2[i] = W2[i];
    for (int i = threadIdx.x; i < F1; i += blockDim.x) sb1[i] = b1[i];
    __syncthreads();
    int n = blockIdx.x * blockDim.x + threadIdx.x;
    if (n >= N_NODES) return;

    float di = g_dinv[n];
    float sl = di * di;
    float o0 = 0.0f, o1 = 0.0f, o2 = 0.0f, o3 = 0.0f;
    const float4* ag = reinterpret_cast<const float4*>(g_agg1 + n * F1);
    const float4* xw = reinterpret_cast<const float4*>(g_xw1 + n * F1);
#pragma unroll
    for (int q = 0; q < F1 / 4; q++) {
        float4 a = ag[q];
        float4 x = xw[q];
        float hv[4];
        hv[0] = tanhf(a.x + x.x * sl + sb1[4 * q + 0]);
        hv[1] = tanhf(a.y + x.y * sl + sb1[4 * q + 1]);
        hv[2] = tanhf(a.z + x.z * sl + sb1[4 * q + 2]);
        hv[3] = tanhf(a.w + x.w * sl + sb1[4 * q + 3]);
#pragma unroll
        for (int r = 0; r < 4; r++) {
            const float* w = &sW2[(4 * q + r) * F2];
            o0 = fmaf(hv[r], w[0], o0);
            o1 = fmaf(hv[r], w[1], o1);
            o2 = fmaf(hv[r], w[2], o2);
            o3 = fmaf(hv[r], w[3], o3);
        }
    }
    *reinterpret_cast<float4*>(g_xw2 + n * F2) = make_float4(o0, o1, o2, o3);
}

// ---------------- K7: scatter layer-2 (1 thread / edge, v4 red) ------------
__global__ void k_scat2() {
    int e = blockIdx.x * blockDim.x + threadIdx.x;
    if (e >= N_EDGES) return;
    int s = g_src[e], d = g_dst[e];
    float nrm = g_dinv[s] * g_dinv[d];
    float4 v = *reinterpret_cast<const float4*>(g_xw2 + s * F2);
    red_v4(g_agg2 + d * F2, v.x * nrm, v.y * nrm, v.z * nrm, v.w * nrm);
}

// ---------------- K8: h2 = tanh(...); xw3 = h2 @ W3 ------------------------
__global__ void k_l3(const float* __restrict__ b2, const float* __restrict__ W3) {
    __shared__ float sW3[F2 * F3];  // 8
    __shared__ float sb2[F2];
    for (int i = threadIdx.x; i < F2 * F3; i += blockDim.x) sW3[i] = W3[i];
    for (int i = threadIdx.x; i < F2; i += blockDim.x) sb2[i] = b2[i];
    __syncthreads();
    int n = blockIdx.x * blockDim.x + threadIdx.x;
    if (n >= N_NODES) return;

    float di = g_dinv[n];
    float sl = di * di;
    float4 a = *reinterpret_cast<const float4*>(g_agg2 + n * F2);
    float4 x = *reinterpret_cast<const float4*>(g_xw2 + n * F2);
    float h2v[4];
    h2v[0] = tanhf(a.x + x.x * sl + sb2[0]);
    h2v[1] = tanhf(a.y + x.y * sl + sb2[1]);
    h2v[2] = tanhf(a.z + x.z * sl + sb2[2]);
    h2v[3] = tanhf(a.w + x.w * sl + sb2[3]);
    float o0 = 0.0f, o1 = 0.0f;
#pragma unroll
    for (int f = 0; f < F2; f++) {
        o0 = fmaf(h2v[f], sW3[f * F3 + 0], o0);
        o1 = fmaf(h2v[f], sW3[f * F3 + 1], o1);
    }
    g_xw3[n * F3 + 0] = o0;
    g_xw3[n * F3 + 1] = o1;
}

// ---------------- K9: scatter layer-3 (1 thread / edge, v2 red) ------------
__global__ void k_scat3() {
    int e = blockIdx.x * blockDim.x + threadIdx.x;
    if (e >= N_EDGES) return;
    int s = g_src[e], d = g_dst[e];
    float nrm = g_dinv[s] * g_dinv[d];
    float v0 = g_xw3[s * F3 + 0] * nrm;
    float v1 = g_xw3[s * F3 + 1] * nrm;
    red_v2(g_agg3 + d * F3, v0, v1);
}

// ---------------- K10: h3 = tanh(...); out = h3 @ Wc + bc ------------------
// d_out layout: out[100000,8] then h3[100000,2] (flattened tuple).
__global__ void k_final(const float* __restrict__ b3, const float* __restrict__ Wc,
                        const float* __restrict__ bc, float* __restrict__ out) {
    __shared__ float sWc[F3 * NC];  // 16
    __shared__ float sbc[NC];
    __shared__ float sb3[F3];
    for (int i = threadIdx.x; i < F3 * NC; i += blockDim.x) sWc[i] = Wc[i];
    for (int i = threadIdx.x; i < NC; i += blockDim.x) sbc[i] = bc[i];
    for (int i = threadIdx.x; i < F3; i += blockDim.x) sb3[i] = b3[i];
    __syncthreads();
    int n = blockIdx.x * blockDim.x + threadIdx.x;
    if (n >= N_NODES) return;

    float di = g_dinv[n];
    float sl = di * di;
    float h3x = tanhf(g_agg3[n * F3 + 0] + g_xw3[n * F3 + 0] * sl + sb3[0]);
    float h3y = tanhf(g_agg3[n * F3 + 1] + g_xw3[n * F3 + 1] * sl + sb3[1]);

    float o[NC];
#pragma unroll
    for (int j = 0; j < NC; j++)
        o[j] = fmaf(h3x, sWc[j], fmaf(h3y, sWc[NC + j], sbc[j]));

    float4* op = reinterpret_cast<float4*>(out + (size_t)n * NC);
    op[0] = make_float4(o[0], o[1], o[2], o[3]);
    op[1] = make_float4(o[4], o[5], o[6], o[7]);

    float2* hp = reinterpret_cast<float2*>(out + (size_t)N_NODES * NC + (size_t)n * F3);
    hp[0] = make_float2(h3x, h3y);
}

// ---------------- host ------------------------------------------------------
extern "C" void kernel_launch(void* const* d_in, const int* in_sizes, int n_in,
                              void* d_out, int out_size) {
    const float* h  = (const float*)d_in[0];
    const void*  ei = d_in[1];
    const float* W1 = (const float*)d_in[2];
    const float* b1 = (const float*)d_in[3];
    const float* W2 = (const float*)d_in[4];
    const float* b2 = (const float*)d_in[5];
    const float* W3 = (const float*)d_in[6];
    const float* b3 = (const float*)d_in[7];
    const float* Wc = (const float*)d_in[8];
    const float* bc = (const float*)d_in[9];
    float* out = (float*)d_out;

    const int T = 256;
    k_detect<<<1, 256>>>((const unsigned int*)ei);
    k_zero<<<1024, T>>>();
    k_edges<<<(N_EDGES + T - 1) / T, T>>>((const int*)ei);
    k_dinv<<<(N_NODES + T - 1) / T, T>>>();
    k_xw1<<<(N_NODES + T - 1) / T, T>>>(h, W1);
    k_scat1<<<(N_EDGES * 4 + T - 1) / T, T>>>();
    k_l2<<<(N_NODES + T - 1) / T, T>>>(b1, W2);
    k_scat2<<<(N_EDGES + T - 1) / T, T>>>();
    k_l3<<<(N_NODES + T - 1) / T, T>>>(b2, W3);
    k_scat3<<<(N_EDGES + T - 1) / T, T>>>();
    k_final<<<(N_NODES + T - 1) / T, T>>>(b3, Wc, bc, out);
}

// round 2
// speedup vs baseline: 1.0733x; 1.0733x over previous
#include <cuda_runtime.h>

#define N_NODES 100000
#define N_EDGES 3200000
#define NFEAT   128
#define F1      16
#define F2      4
#define F3      2
#define NC      8

#define SCB     512
#define NBLK    ((N_NODES + SCB - 1) / SCB)   // 196

// ---------------- scratch (device globals; no allocation allowed) ----------
__device__ int g_is64;
__device__ __align__(16) int   g_src[N_EDGES];
__device__ __align__(16) int   g_dst[N_EDGES];
__device__ __align__(16) int   g_cnt[N_NODES];
__device__ __align__(16) int   g_off[N_NODES];
__device__ __align__(16) int   g_cur[N_NODES];
__device__ __align__(16) int   g_bsum[NBLK];
__device__ __align__(16) int   g_boff[NBLK];
__device__ __align__(16) float g_dinv[N_NODES];
__device__ __align__(16) int2  g_csr[N_EDGES];           // .x = src, .y = bits(norm)
__device__ __align__(16) float g_xw1[N_NODES * F1];
__device__ __align__(16) float g_xw2[N_NODES * F2];
__device__ __align__(16) float2 g_xw3[N_NODES];

// ---------------- K0: detect int64 vs int32 + zero degree counts -----------
__global__ void k_init(const unsigned int* __restrict__ w) {
    int i = blockIdx.x * blockDim.x + threadIdx.x;
    int stride = gridDim.x * blockDim.x;
    for (int j = i; j < N_NODES; j += stride) g_cnt[j] = 0;
    if (blockIdx.x == 0) {
        __shared__ unsigned int s;
        if (threadIdx.x == 0) s = 0u;
        __syncthreads();
        unsigned int nz = 0;
        for (int k = threadIdx.x; k < 2048; k += blockDim.x) nz |= w[2 * k + 1];
        atomicOr(&s, nz);
        __syncthreads();
        if (threadIdx.x == 0) g_is64 = (s == 0u) ? 1 : 0;
    }
}

// ---------------- K1: convert edges to int32 + degree count ----------------
__global__ void k_edges(const void* __restrict__ ei) {
    int e = blockIdx.x * blockDim.x + threadIdx.x;
    if (e >= N_EDGES) return;
    int s, d;
    if (g_is64) {
        const long long* p = (const long long*)ei;
        s = (int)p[e];
        d = (int)p[N_EDGES + e];
    } else {
        const int* p = (const int*)ei;
        s = p[e];
        d = p[N_EDGES + e];
    }
    g_src[e] = s;
    g_dst[e] = d;
    atomicAdd(&g_cnt[d], 1);
}

// ---------------- K2a: per-block exclusive scan of counts ------------------
__global__ void k_scan1() {
    __shared__ int s[SCB];
    int b = blockIdx.x, t = threadIdx.x;
    int i = b * SCB + t;
    int v = (i < N_NODES) ? g_cnt[i] : 0;
    s[t] = v;
    __syncthreads();
#pragma unroll
    for (int d = 1; d < SCB; d <<= 1) {
        int add = (t >= d) ? s[t - d] : 0;
        __syncthreads();
        s[t] += add;
        __syncthreads();
    }
    if (i < N_NODES) g_off[i] = s[t] - v;   // exclusive
    if (t == SCB - 1) g_bsum[b] = s[t];
}

// ---------------- K2b: scan of block sums (single block) -------------------
__global__ void k_scan2() {
    __shared__ int s[256];
    int t = threadIdx.x;
    int v = (t < NBLK) ? g_bsum[t] : 0;
    s[t] = v;
    __syncthreads();
#pragma unroll
    for (int d = 1; d < 256; d <<= 1) {
        int add = (t >= d) ? s[t - d] : 0;
        __syncthreads();
        s[t] += add;
        __syncthreads();
    }
    if (t < NBLK) g_boff[t] = s[t] - v;     // exclusive
}

// ---------------- K2c: finalize offsets + cursors + dinv -------------------
__global__ void k_scan3() {
    int n = blockIdx.x * blockDim.x + threadIdx.x;
    if (n >= N_NODES) return;
    int off = g_off[n] + g_boff[n / SCB];
    g_off[n] = off;
    g_cur[n] = off;
    g_dinv[n] = rsqrtf((float)(g_cnt[n] + 1));
}

// ---------------- K3: CSR build (src + edge norm, dst-sorted) --------------
__global__ void k_csr() {
    int e = blockIdx.x * blockDim.x + threadIdx.x;
    if (e >= N_EDGES) return;
    int s = g_src[e], d = g_dst[e];
    int pos = atomicAdd(&g_cur[d], 1);
    float nrm = g_dinv[s] * g_dinv[d];
    g_csr[pos] = make_int2(s, __float_as_int(nrm));
}

// ---------------- K4: xw1 = h @ W1   (100k x 128 @ 128 x 16) ---------------
__global__ void k_xw1(const float* __restrict__ h, const float* __restrict__ W1) {
    __shared__ float sW[NFEAT * F1];   // 8 KB
    for (int i = threadIdx.x; i < NFEAT * F1; i += blockDim.x) sW[i] = W1[i];
    __syncthreads();
    int n = blockIdx.x * blockDim.x + threadIdx.x;
    if (n >= N_NODES) return;

    float acc[F1];
#pragma unroll
    for (int f = 0; f < F1; f++) acc[f] = 0.0f;

    const float4* h4 = reinterpret_cast<const float4*>(h + (size_t)n * NFEAT);
#pragma unroll 4
    for (int k4 = 0; k4 < NFEAT / 4; k4++) {
        float4 hv = h4[k4];
        const float* w = &sW[(k4 * 4) * F1];
#pragma unroll
        for (int f = 0; f < F1; f++) {
            float a = acc[f];
            a = fmaf(hv.x, w[f],          a);
            a = fmaf(hv.y, w[F1 + f],     a);
            a = fmaf(hv.z, w[2 * F1 + f], a);
            a = fmaf(hv.w, w[3 * F1 + f], a);
            acc[f] = a;
        }
    }
    float4* o = reinterpret_cast<float4*>(g_xw1 + n * F1);
#pragma unroll
    for (int q = 0; q < F1 / 4; q++)
        o[q] = make_float4(acc[4 * q], acc[4 * q + 1], acc[4 * q + 2], acc[4 * q + 3]);
}

// ---------------- K5: pull layer-1 + fused (bias,self,tanh) + @W2 ----------
// 8 lanes per node; each lane accumulates all 16 features over its edge slice.
__global__ void k_pull1(const float* __restrict__ b1, const float* __restrict__ W2) {
    __shared__ float sW2[F1 * F2];
    __shared__ float sb1[F1];
    for (int i = threadIdx.x; i < F1 * F2; i += blockDim.x) sW2[i] = W2[i];
    for (int i = threadIdx.x; i < F1; i += blockDim.x) sb1[i] = b1[i];
    __syncthreads();

    int t = blockIdx.x * blockDim.x + threadIdx.x;
    int n = t >> 3;
    int j = t & 7;
    if (n >= N_NODES) return;

    int off = g_off[n], cnt = g_cnt[n];
    float acc[F1];
#pragma unroll
    for (int f = 0; f < F1; f++) acc[f] = 0.0f;

    for (int i = off + j; i < off + cnt; i += 8) {
        int2 e = g_csr[i];
        float nrm = __int_as_float(e.y);
        const float4* p = reinterpret_cast<const float4*>(g_xw1 + e.x * F1);
#pragma unroll
        for (int q = 0; q < 4; q++) {
            float4 v = p[q];
            acc[4 * q + 0] = fmaf(v.x, nrm, acc[4 * q + 0]);
            acc[4 * q + 1] = fmaf(v.y, nrm, acc[4 * q + 1]);
            acc[4 * q + 2] = fmaf(v.z, nrm, acc[4 * q + 2]);
            acc[4 * q + 3] = fmaf(v.w, nrm, acc[4 * q + 3]);
        }
    }
#pragma unroll
    for (int d = 4; d >= 1; d >>= 1)
#pragma unroll
        for (int f = 0; f < F1; f++)
            acc[f] += __shfl_down_sync(0xffffffffu, acc[f], d, 8);

    if (j == 0) {
        float sl = g_dinv[n]; sl *= sl;
        const float4* xp = reinterpret_cast<const float4*>(g_xw1 + n * F1);
        float o0 = 0.0f, o1 = 0.0f, o2 = 0.0f, o3 = 0.0f;
#pragma unroll
        for (int q = 0; q < 4; q++) {
            float4 x = xp[q];
            float xv[4] = {x.x, x.y, x.z, x.w};
#pragma unroll
            for (int r = 0; r < 4; r++) {
                float hv = tanhf(acc[4 * q + r] + xv[r] * sl + sb1[4 * q + r]);
                const float* w = &sW2[(4 * q + r) * F2];
                o0 = fmaf(hv, w[0], o0);
                o1 = fmaf(hv, w[1], o1);
                o2 = fmaf(hv, w[2], o2);
                o3 = fmaf(hv, w[3], o3);
            }
        }
        *reinterpret_cast<float4*>(g_xw2 + n * F2) = make_float4(o0, o1, o2, o3);
    }
}

// ---------------- K6: pull layer-2 + fused + @W3 ---------------------------
// 4 lanes per node.
__global__ void k_pull2(const float* __restrict__ b2, const float* __restrict__ W3) {
    __shared__ float sW3[F2 * F3];
    __shared__ float sb2[F2];
    for (int i = threadIdx.x; i < F2 * F3; i += blockDim.x) sW3[i] = W3[i];
    for (int i = threadIdx.x; i < F2; i += blockDim.x) sb2[i] = b2[i];
    __syncthreads();

    int t = blockIdx.x * blockDim.x + threadIdx.x;
    int n = t >> 2;
    int j = t & 3;
    if (n >= N_NODES) return;

    int off = g_off[n], cnt = g_cnt[n];
    float a0 = 0.0f, a1 = 0.0f, a2 = 0.0f, a3 = 0.0f;
    for (int i = off + j; i < off + cnt; i += 4) {
        int2 e = g_csr[i];
        float nrm = __int_as_float(e.y);
        float4 v = *reinterpret_cast<const float4*>(g_xw2 + e.x * F2);
        a0 = fmaf(v.x, nrm, a0);
        a1 = fmaf(v.y, nrm, a1);
        a2 = fmaf(v.z, nrm, a2);
        a3 = fmaf(v.w, nrm, a3);
    }
#pragma unroll
    for (int d = 2; d >= 1; d >>= 1) {
        a0 += __shfl_down_sync(0xffffffffu, a0, d, 4);
        a1 += __shfl_down_sync(0xffffffffu, a1, d, 4);
        a2 += __shfl_down_sync(0xffffffffu, a2, d, 4);
        a3 += __shfl_down_sync(0xffffffffu, a3, d, 4);
    }
    if (j == 0) {
        float sl = g_dinv[n]; sl *= sl;
        float4 x = *reinterpret_cast<const float4*>(g_xw2 + n * F2);
        float h0 = tanhf(a0 + x.x * sl + sb2[0]);
        float h1 = tanhf(a1 + x.y * sl + sb2[1]);
        float h2 = tanhf(a2 + x.z * sl + sb2[2]);
        float h3 = tanhf(a3 + x.w * sl + sb2[3]);
        float o0 = fmaf(h0, sW3[0], fmaf(h1, sW3[2], fmaf(h2, sW3[4], h3 * sW3[6])));
        float o1 = fmaf(h0, sW3[1], fmaf(h1, sW3[3], fmaf(h2, sW3[5], h3 * sW3[7])));
        g_xw3[n] = make_float2(o0, o1);
    }
}

// ---------------- K7: pull layer-3 + fused + classifier --------------------
// 4 lanes per node. d_out layout: out[100000,8] then h3[100000,2].
__global__ void k_pull3(const float* __restrict__ b3, const float* __restrict__ Wc,
                        const float* __restrict__ bc, float* __restrict__ out) {
    __shared__ float sWc[F3 * NC];
    __shared__ float sbc[NC];
    __shared__ float sb3[F3];
    for (int i = threadIdx.x; i < F3 * NC; i += blockDim.x) sWc[i] = Wc[i];
    for (int i = threadIdx.x; i < NC; i += blockDim.x) sbc[i] = bc[i];
    for (int i = threadIdx.x; i < F3; i += blockDim.x) sb3[i] = b3[i];
    __syncthreads();

    int t = blockIdx.x * blockDim.x + threadIdx.x;
    int n = t >> 2;
    int j = t & 3;
    if (n >= N_NODES) return;

    int off = g_off[n], cnt = g_cnt[n];
    float a0 = 0.0f, a1 = 0.0f;
    for (int i = off + j; i < off + cnt; i += 4) {
        int2 e = g_csr[i];
        float nrm = __int_as_float(e.y);
        float2 v = g_xw3[e.x];
        a0 = fmaf(v.x, nrm, a0);
        a1 = fmaf(v.y, nrm, a1);
    }
#pragma unroll
    for (int d = 2; d >= 1; d >>= 1) {
        a0 += __shfl_down_sync(0xffffffffu, a0, d, 4);
        a1 += __shfl_down_sync(0xffffffffu, a1, d, 4);
    }
    if (j == 0) {
        float sl = g_dinv[n]; sl *= sl;
        float2 x = g_xw3[n];
        float h3x = tanhf(a0 + x.x * sl + sb3[0]);
        float h3y = tanhf(a1 + x.y * sl + sb3[1]);

        float o[NC];
#pragma unroll
        for (int k = 0; k < NC; k++)
            o[k] = fmaf(h3x, sWc[k], fmaf(h3y, sWc[NC + k], sbc[k]));

        float4* op = reinterpret_cast<float4*>(out + (size_t)n * NC);
        op[0] = make_float4(o[0], o[1], o[2], o[3]);
        op[1] = make_float4(o[4], o[5], o[6], o[7]);
        *reinterpret_cast<float2*>(out + (size_t)N_NODES * NC + (size_t)n * F3) =
            make_float2(h3x, h3y);
    }
}

// ---------------- host ------------------------------------------------------
extern "C" void kernel_launch(void* const* d_in, const int* in_sizes, int n_in,
                              void* d_out, int out_size) {
    const float* h  = (const float*)d_in[0];
    const void*  ei = d_in[1];
    const float* W1 = (const float*)d_in[2];
    const float* b1 = (const float*)d_in[3];
    const float* W2 = (const float*)d_in[4];
    const float* b2 = (const float*)d_in[5];
    const float* W3 = (const float*)d_in[6];
    const float* b3 = (const float*)d_in[7];
    const float* Wc = (const float*)d_in[8];
    const float* bc = (const float*)d_in[9];
    float* out = (float*)d_out;

    const int T = 256;
    k_init<<<400, T>>>((const unsigned int*)ei);
    k_edges<<<(N_EDGES + T - 1) / T, T>>>(ei);
    k_scan1<<<NBLK, SCB>>>();
    k_scan2<<<1, 256>>>();
    k_scan3<<<(N_NODES + T - 1) / T, T>>>();
    k_csr<<<(N_EDGES + T - 1) / T, T>>>();
    k_xw1<<<(N_NODES + T - 1) / T, T>>>(h, W1);
    k_pull1<<<(N_NODES * 8 + T - 1) / T, T>>>(b1, W2);
    k_pull2<<<(N_NODES * 4 + T - 1) / T, T>>>(b2, W3);
    k_pull3<<<(N_NODES * 4 + T - 1) / T, T>>>(b3, Wc, bc, out);
}

// round 3
// speedup vs baseline: 1.3981x; 1.3026x over previous
#include <cuda_runtime.h>

#define N_NODES 100000
#define N_EDGES 3200000
#define NFEAT   128
#define F1      16
#define F2      4
#define F3      2
#define NC      8
#define FULL    0xffffffffu

// ---------------- scratch (device globals; no allocation allowed) ----------
__device__ int g_is64;
__device__ int g_total;
__device__ __align__(16) int    g_src[N_EDGES];
__device__ __align__(16) int    g_dst[N_EDGES];
__device__ __align__(16) int    g_cnt[N_NODES];
__device__ __align__(16) int2   g_nfo[N_NODES];     // (off, cnt)
__device__ __align__(16) int    g_cur[N_NODES];
__device__ __align__(16) float  g_dinv[N_NODES];
__device__ __align__(16) int    g_csr[N_EDGES];     // src only (norm is separable)
__device__ __align__(16) float  g_y1[N_NODES * F1]; // (h@W1)*dinv
__device__ __align__(16) float  g_y2[N_NODES * F2]; // xw2*dinv
__device__ __align__(16) float2 g_y3[N_NODES];      // xw3*dinv

// ---------------- K0: detect int64 vs int32 + zero counters ----------------
__global__ void k_init(const unsigned int* __restrict__ w) {
    int i = blockIdx.x * blockDim.x + threadIdx.x;
    int stride = gridDim.x * blockDim.x;
    for (int j = i; j < N_NODES; j += stride) g_cnt[j] = 0;
    if (i == 0) g_total = 0;
    if (blockIdx.x == 0) {
        __shared__ unsigned int s;
        if (threadIdx.x == 0) s = 0u;
        __syncthreads();
        unsigned int nz = 0;
        for (int k = threadIdx.x; k < 2048; k += blockDim.x) nz |= w[2 * k + 1];
        atomicOr(&s, nz);
        __syncthreads();
        if (threadIdx.x == 0) g_is64 = (s == 0u) ? 1 : 0;
    }
}

// ---------------- K1: convert edges to int32 + degree count ----------------
__global__ void k_edges(const void* __restrict__ ei) {
    int e = blockIdx.x * blockDim.x + threadIdx.x;
    if (e >= N_EDGES) return;
    int s, d;
    if (g_is64) {
        const long long* p = (const long long*)ei;
        s = (int)p[e];
        d = (int)p[N_EDGES + e];
    } else {
        const int* p = (const int*)ei;
        s = p[e];
        d = p[N_EDGES + e];
    }
    g_src[e] = s;
    g_dst[e] = d;
    atomicAdd(&g_cnt[d], 1);
}

// ---------------- K2: offsets (warp-aggregated alloc) + dinv + y1 ----------
// y1 = (h @ W1) * dinv[n]   (100k x 128 @ 128 x 16)
__global__ void k_xw1off(const float* __restrict__ h, const float* __restrict__ W1) {
    __shared__ float sW[NFEAT * F1];   // 8 KB
    for (int i = threadIdx.x; i < NFEAT * F1; i += blockDim.x) sW[i] = W1[i];
    __syncthreads();

    int n = blockIdx.x * blockDim.x + threadIdx.x;
    int lane = threadIdx.x & 31;
    bool valid = (n < N_NODES);

    // --- segment offset allocation (order across warps is irrelevant) ---
    int cnt = valid ? g_cnt[n] : 0;
    int incl = cnt;
#pragma unroll
    for (int d = 1; d < 32; d <<= 1) {
        int v = __shfl_up_sync(FULL, incl, d);
        if (lane >= d) incl += v;
    }
    int base = 0;
    if (lane == 31) base = atomicAdd(&g_total, incl);
    base = __shfl_sync(FULL, base, 31);
    int off = base + incl - cnt;

    if (!valid) return;
    g_nfo[n] = make_int2(off, cnt);
    g_cur[n] = off;
    float dinv = rsqrtf((float)(cnt + 1));
    g_dinv[n] = dinv;

    // --- GEMM row ---
    float acc[F1];
#pragma unroll
    for (int f = 0; f < F1; f++) acc[f] = 0.0f;

    const float4* h4 = reinterpret_cast<const float4*>(h + (size_t)n * NFEAT);
#pragma unroll 4
    for (int k4 = 0; k4 < NFEAT / 4; k4++) {
        float4 hv = h4[k4];
        const float* w = &sW[(k4 * 4) * F1];
#pragma unroll
        for (int f = 0; f < F1; f++) {
            float a = acc[f];
            a = fmaf(hv.x, w[f],          a);
            a = fmaf(hv.y, w[F1 + f],     a);
            a = fmaf(hv.z, w[2 * F1 + f], a);
            a = fmaf(hv.w, w[3 * F1 + f], a);
            acc[f] = a;
        }
    }
    float4* o = reinterpret_cast<float4*>(g_y1 + n * F1);
#pragma unroll
    for (int q = 0; q < F1 / 4; q++)
        o[q] = make_float4(acc[4 * q] * dinv, acc[4 * q + 1] * dinv,
                           acc[4 * q + 2] * dinv, acc[4 * q + 3] * dinv);
}

// ---------------- K3: CSR build (src only, dst-sorted) ---------------------
__global__ void k_csr() {
    int e = blockIdx.x * blockDim.x + threadIdx.x;
    if (e >= N_EDGES) return;
    int s = g_src[e], d = g_dst[e];
    int pos = atomicAdd(&g_cur[d], 1);
    g_csr[pos] = s;
}

// ---------------- K4: pull layer-1 + fused (tanh) + @W2 --------------------
// 8 lanes per node = 2 edge-slots x 4 feature-quarters.
// agg = dinv[n] * (sum_in y1[src] + y1[n]);  h1 = tanh(agg + b1);  y2 = (h1@W2)*dinv.
__global__ void k_pull1(const float* __restrict__ b1, const float* __restrict__ W2) {
    __shared__ float sW2[F1 * F2];
    __shared__ float sb1[F1];
    for (int i = threadIdx.x; i < F1 * F2; i += blockDim.x) sW2[i] = W2[i];
    for (int i = threadIdx.x; i < F1; i += blockDim.x) sb1[i] = b1[i];
    __syncthreads();

    int t = blockIdx.x * blockDim.x + threadIdx.x;   // exactly 800000 threads
    int n = t >> 3;
    int j = t & 7;
    int s = j >> 2;       // edge slot 0/1
    int q = j & 3;        // feature quarter

    int2 nfo = g_nfo[n];
    int off = nfo.x, cnt = nfo.y;

    float a0 = 0.0f, a1 = 0.0f, a2 = 0.0f, a3 = 0.0f;
    for (int i = off + s; i < off + cnt; i += 2) {
        int src = __ldg(&g_csr[i]);
        float4 v = *reinterpret_cast<const float4*>(g_y1 + src * F1 + q * 4);
        a0 += v.x; a1 += v.y; a2 += v.z; a3 += v.w;
    }
    // combine the two edge slots (width-8 groups)
    a0 += __shfl_down_sync(FULL, a0, 4, 8);
    a1 += __shfl_down_sync(FULL, a1, 4, 8);
    a2 += __shfl_down_sync(FULL, a2, 4, 8);
    a3 += __shfl_down_sync(FULL, a3, 4, 8);

    // lanes j=0..3 now hold quarter q=j sums; compute partial epilogue on each
    float dinv = g_dinv[n];
    float4 yv = *reinterpret_cast<const float4*>(g_y1 + n * F1 + q * 4);
    float h0 = tanhf(dinv * (a0 + yv.x) + sb1[4 * q + 0]);
    float h1 = tanhf(dinv * (a1 + yv.y) + sb1[4 * q + 1]);
    float h2 = tanhf(dinv * (a2 + yv.z) + sb1[4 * q + 2]);
    float h3 = tanhf(dinv * (a3 + yv.w) + sb1[4 * q + 3]);

    float o0, o1, o2, o3;
    {
        const float* w0 = &sW2[(4 * q + 0) * F2];
        const float* w1 = &sW2[(4 * q + 1) * F2];
        const float* w2 = &sW2[(4 * q + 2) * F2];
        const float* w3 = &sW2[(4 * q + 3) * F2];
        o0 = fmaf(h0, w0[0], fmaf(h1, w1[0], fmaf(h2, w2[0], h3 * w3[0])));
        o1 = fmaf(h0, w0[1], fmaf(h1, w1[1], fmaf(h2, w2[1], h3 * w3[1])));
        o2 = fmaf(h0, w0[2], fmaf(h1, w1[2], fmaf(h2, w2[2], h3 * w3[2])));
        o3 = fmaf(h0, w0[3], fmaf(h1, w1[3], fmaf(h2, w2[3], h3 * w3[3])));
    }
    // reduce partials across the 4 quarter-lanes (width-4 groups)
    o0 += __shfl_down_sync(FULL, o0, 2, 4);
    o1 += __shfl_down_sync(FULL, o1, 2, 4);
    o2 += __shfl_down_sync(FULL, o2, 2, 4);
    o3 += __shfl_down_sync(FULL, o3, 2, 4);
    o0 += __shfl_down_sync(FULL, o0, 1, 4);
    o1 += __shfl_down_sync(FULL, o1, 1, 4);
    o2 += __shfl_down_sync(FULL, o2, 1, 4);
    o3 += __shfl_down_sync(FULL, o3, 1, 4);

    if (j == 0)
        *reinterpret_cast<float4*>(g_y2 + n * F2) =
            make_float4(o0 * dinv, o1 * dinv, o2 * dinv, o3 * dinv);
}

// ---------------- K5: pull layer-2 + fused + @W3 ---------------------------
__global__ void k_pull2(const float* __restrict__ b2, const float* __restrict__ W3) {
    __shared__ float sW3[F2 * F3];
    __shared__ float sb2[F2];
    for (int i = threadIdx.x; i < F2 * F3; i += blockDim.x) sW3[i] = W3[i];
    for (int i = threadIdx.x; i < F2; i += blockDim.x) sb2[i] = b2[i];
    __syncthreads();

    int t = blockIdx.x * blockDim.x + threadIdx.x;
    int n = t >> 2;
    int j = t & 3;
    if (n >= N_NODES) return;

    int2 nfo = g_nfo[n];
    int off = nfo.x, cnt = nfo.y;
    float a0 = 0.0f, a1 = 0.0f, a2 = 0.0f, a3 = 0.0f;
    for (int i = off + j; i < off + cnt; i += 4) {
        int src = __ldg(&g_csr[i]);
        float4 v = *reinterpret_cast<const float4*>(g_y2 + src * F2);
        a0 += v.x; a1 += v.y; a2 += v.z; a3 += v.w;
    }
#pragma unroll
    for (int d = 2; d >= 1; d >>= 1) {
        a0 += __shfl_down_sync(FULL, a0, d, 4);
        a1 += __shfl_down_sync(FULL, a1, d, 4);
        a2 += __shfl_down_sync(FULL, a2, d, 4);
        a3 += __shfl_down_sync(FULL, a3, d, 4);
    }
    if (j == 0) {
        float dinv = g_dinv[n];
        float4 yv = *reinterpret_cast<const float4*>(g_y2 + n * F2);
        float h0 = tanhf(dinv * (a0 + yv.x) + sb2[0]);
        float h1 = tanhf(dinv * (a1 + yv.y) + sb2[1]);
        float h2 = tanhf(dinv * (a2 + yv.z) + sb2[2]);
        float h3 = tanhf(dinv * (a3 + yv.w) + sb2[3]);
        float o0 = fmaf(h0, sW3[0], fmaf(h1, sW3[2], fmaf(h2, sW3[4], h3 * sW3[6])));
        float o1 = fmaf(h0, sW3[1], fmaf(h1, sW3[3], fmaf(h2, sW3[5], h3 * sW3[7])));
        g_y3[n] = make_float2(o0 * dinv, o1 * dinv);
    }
}

// ---------------- K6: pull layer-3 + fused + classifier --------------------
// d_out layout: out[100000,8] then h3[100000,2].
__global__ void k_pull3(const float* __restrict__ b3, const float* __restrict__ Wc,
                        const float* __restrict__ bc, float* __restrict__ out) {
    __shared__ float sWc[F3 * NC];
    __shared__ float sbc[NC];
    __shared__ float sb3[F3];
    for (int i = threadIdx.x; i < F3 * NC; i += blockDim.x) sWc[i] = Wc[i];
    for (int i = threadIdx.x; i < NC; i += blockDim.x) sbc[i] = bc[i];
    for (int i = threadIdx.x; i < F3; i += blockDim.x) sb3[i] = b3[i];
    __syncthreads();

    int t = blockIdx.x * blockDim.x + threadIdx.x;
    int n = t >> 2;
    int j = t & 3;
    if (n >= N_NODES) return;

    int2 nfo = g_nfo[n];
    int off = nfo.x, cnt = nfo.y;
    float a0 = 0.0f, a1 = 0.0f;
    for (int i = off + j; i < off + cnt; i += 4) {
        int src = __ldg(&g_csr[i]);
        float2 v = g_y3[src];
        a0 += v.x; a1 += v.y;
    }
#pragma unroll
    for (int d = 2; d >= 1; d >>= 1) {
        a0 += __shfl_down_sync(FULL, a0, d, 4);
        a1 += __shfl_down_sync(FULL, a1, d, 4);
    }
    if (j == 0) {
        float dinv = g_dinv[n];
        float2 yv = g_y3[n];
        float h3x = tanhf(dinv * (a0 + yv.x) + sb3[0]);
        float h3y = tanhf(dinv * (a1 + yv.y) + sb3[1]);

        float o[NC];
#pragma unroll
        for (int k = 0; k < NC; k++)
            o[k] = fmaf(h3x, sWc[k], fmaf(h3y, sWc[NC + k], sbc[k]));

        float4* op = reinterpret_cast<float4*>(out + (size_t)n * NC);
        op[0] = make_float4(o[0], o[1], o[2], o[3]);
        op[1] = make_float4(o[4], o[5], o[6], o[7]);
        *reinterpret_cast<float2*>(out + (size_t)N_NODES * NC + (size_t)n * F3) =
            make_float2(h3x, h3y);
    }
}

// ---------------- host ------------------------------------------------------
extern "C" void kernel_launch(void* const* d_in, const int* in_sizes, int n_in,
                              void* d_out, int out_size) {
    const float* h  = (const float*)d_in[0];
    const void*  ei = d_in[1];
    const float* W1 = (const float*)d_in[2];
    const float* b1 = (const float*)d_in[3];
    const float* W2 = (const float*)d_in[4];
    const float* b2 = (const float*)d_in[5];
    const float* W3 = (const float*)d_in[6];
    const float* b3 = (const float*)d_in[7];
    const float* Wc = (const float*)d_in[8];
    const float* bc = (const float*)d_in[9];
    float* out = (float*)d_out;

    const int T = 256;
    k_init  <<<400, T>>>((const unsigned int*)ei);
    k_edges <<<(N_EDGES + T - 1) / T, T>>>(ei);
    k_xw1off<<<(N_NODES + T - 1) / T, T>>>(h, W1);
    k_csr   <<<(N_EDGES + T - 1) / T, T>>>();
    k_pull1 <<<(N_NODES * 8) / T, T>>>(b1, W2);
    k_pull2 <<<(N_NODES * 4 + T - 1) / T, T>>>(b2, W3);
    k_pull3 <<<(N_NODES * 4 + T - 1) / T, T>>>(b3, Wc, bc, out);
}

// round 4
// speedup vs baseline: 1.4182x; 1.0144x over previous
#include <cuda_runtime.h>

#define N_NODES 100000
#define N_EDGES 3200000
#define NFEAT   128
#define F1      16
#define F2      4
#define F3      2
#define NC      8
#define FULL    0xffffffffu

// ---------------- scratch (device globals; no allocation allowed) ----------
__device__ int g_is64;
__device__ int g_total;
__device__ __align__(16) int    g_src[N_EDGES];
__device__ __align__(16) int    g_dst[N_EDGES];
__device__ __align__(16) int    g_rank[N_EDGES];    // rank of edge within its dst segment
__device__ __align__(16) int    g_cnt[N_NODES];
__device__ __align__(16) int2   g_nfo[N_NODES];     // (off, cnt)
__device__ __align__(16) float  g_dinv[N_NODES];
__device__ __align__(16) int    g_csr[N_EDGES];     // src only (norm is separable)
__device__ __align__(16) float  g_y1[N_NODES * F1]; // (h@W1)*dinv
__device__ __align__(16) float  g_y2[N_NODES * F2]; // xw2*dinv
__device__ __align__(16) float2 g_y3[N_NODES];      // xw3*dinv

// ---------------- K0: detect int64 vs int32 + zero counters ----------------
__global__ void k_init(const unsigned int* __restrict__ w) {
    int i = blockIdx.x * blockDim.x + threadIdx.x;
    int stride = gridDim.x * blockDim.x;
    for (int j = i; j < N_NODES; j += stride) g_cnt[j] = 0;
    if (i == 0) g_total = 0;
    if (blockIdx.x == 0) {
        __shared__ unsigned int s;
        if (threadIdx.x == 0) s = 0u;
        __syncthreads();
        unsigned int nz = 0;
        for (int k = threadIdx.x; k < 2048; k += blockDim.x) nz |= w[2 * k + 1];
        atomicOr(&s, nz);
        __syncthreads();
        if (threadIdx.x == 0) g_is64 = (s == 0u) ? 1 : 0;
    }
}

// ---------------- K1: convert edges to int32 + degree count + rank ---------
// atomicAdd's return value IS the CSR rank of this edge within its dst.
__global__ void k_edges(const void* __restrict__ ei) {
    int e = blockIdx.x * blockDim.x + threadIdx.x;
    if (e >= N_EDGES) return;
    int s, d;
    if (g_is64) {
        const long long* p = (const long long*)ei;
        s = (int)p[e];
        d = (int)p[N_EDGES + e];
    } else {
        const int* p = (const int*)ei;
        s = p[e];
        d = p[N_EDGES + e];
    }
    g_src[e] = s;
    g_dst[e] = d;
    g_rank[e] = atomicAdd(&g_cnt[d], 1);
}

// ---------------- K2: offsets (warp-aggregated alloc) + dinv + y1 ----------
// y1 = (h @ W1) * dinv[n]   (100k x 128 @ 128 x 16)
__global__ void k_xw1off(const float* __restrict__ h, const float* __restrict__ W1) {
    __shared__ float sW[NFEAT * F1];   // 8 KB
    for (int i = threadIdx.x; i < NFEAT * F1; i += blockDim.x) sW[i] = W1[i];
    __syncthreads();

    int n = blockIdx.x * blockDim.x + threadIdx.x;
    int lane = threadIdx.x & 31;
    bool valid = (n < N_NODES);

    // --- segment offset allocation (order across warps is irrelevant) ---
    int cnt = valid ? g_cnt[n] : 0;
    int incl = cnt;
#pragma unroll
    for (int d = 1; d < 32; d <<= 1) {
        int v = __shfl_up_sync(FULL, incl, d);
        if (lane >= d) incl += v;
    }
    int base = 0;
    if (lane == 31) base = atomicAdd(&g_total, incl);
    base = __shfl_sync(FULL, base, 31);
    int off = base + incl - cnt;

    if (!valid) return;
    g_nfo[n] = make_int2(off, cnt);
    float dinv = rsqrtf((float)(cnt + 1));
    g_dinv[n] = dinv;

    // --- GEMM row ---
    float acc[F1];
#pragma unroll
    for (int f = 0; f < F1; f++) acc[f] = 0.0f;

    const float4* h4 = reinterpret_cast<const float4*>(h + (size_t)n * NFEAT);
#pragma unroll 4
    for (int k4 = 0; k4 < NFEAT / 4; k4++) {
        float4 hv = h4[k4];
        const float* w = &sW[(k4 * 4) * F1];
#pragma unroll
        for (int f = 0; f < F1; f++) {
            float a = acc[f];
            a = fmaf(hv.x, w[f],          a);
            a = fmaf(hv.y, w[F1 + f],     a);
            a = fmaf(hv.z, w[2 * F1 + f], a);
            a = fmaf(hv.w, w[3 * F1 + f], a);
            acc[f] = a;
        }
    }
    float4* o = reinterpret_cast<float4*>(g_y1 + n * F1);
#pragma unroll
    for (int q = 0; q < F1 / 4; q++)
        o[q] = make_float4(acc[4 * q] * dinv, acc[4 * q + 1] * dinv,
                           acc[4 * q + 2] * dinv, acc[4 * q + 3] * dinv);
}

// ---------------- K3: CSR build — atomic-free scatter, 4 edges/thread ------
__global__ void k_csr() {
    int e4 = blockIdx.x * blockDim.x + threadIdx.x;   // 800000 threads exactly
    if (e4 >= N_EDGES / 4) return;
    int4 s = reinterpret_cast<const int4*>(g_src)[e4];
    int4 d = reinterpret_cast<const int4*>(g_dst)[e4];
    int4 r = reinterpret_cast<const int4*>(g_rank)[e4];
    g_csr[__ldg(&g_nfo[d.x].x) + r.x] = s.x;
    g_csr[__ldg(&g_nfo[d.y].x) + r.y] = s.y;
    g_csr[__ldg(&g_nfo[d.z].x) + r.z] = s.z;
    g_csr[__ldg(&g_nfo[d.w].x) + r.w] = s.w;
}

// ---------------- K4: pull layer-1 + fused (tanh) + @W2 --------------------
// 8 lanes per node = 2 edge-slots x 4 feature-quarters.
__global__ void k_pull1(const float* __restrict__ b1, const float* __restrict__ W2) {
    __shared__ float sW2[F1 * F2];
    __shared__ float sb1[F1];
    for (int i = threadIdx.x; i < F1 * F2; i += blockDim.x) sW2[i] = W2[i];
    for (int i = threadIdx.x; i < F1; i += blockDim.x) sb1[i] = b1[i];
    __syncthreads();

    int t = blockIdx.x * blockDim.x + threadIdx.x;   // exactly 800000 threads
    int n = t >> 3;
    int j = t & 7;
    int s = j >> 2;       // edge slot 0/1
    int q = j & 3;        // feature quarter

    int2 nfo = g_nfo[n];
    int off = nfo.x, cnt = nfo.y;

    float a0 = 0.0f, a1 = 0.0f, a2 = 0.0f, a3 = 0.0f;
    for (int i = off + s; i < off + cnt; i += 2) {
        int src = __ldg(&g_csr[i]);
        float4 v = *reinterpret_cast<const float4*>(g_y1 + src * F1 + q * 4);
        a0 += v.x; a1 += v.y; a2 += v.z; a3 += v.w;
    }
    // combine the two edge slots (width-8 groups)
    a0 += __shfl_down_sync(FULL, a0, 4, 8);
    a1 += __shfl_down_sync(FULL, a1, 4, 8);
    a2 += __shfl_down_sync(FULL, a2, 4, 8);
    a3 += __shfl_down_sync(FULL, a3, 4, 8);

    // lanes j=0..3 hold quarter q=j sums; partial epilogue on each
    float dinv = g_dinv[n];
    float4 yv = *reinterpret_cast<const float4*>(g_y1 + n * F1 + q * 4);
    float h0 = tanhf(dinv * (a0 + yv.x) + sb1[4 * q + 0]);
    float h1 = tanhf(dinv * (a1 + yv.y) + sb1[4 * q + 1]);
    float h2 = tanhf(dinv * (a2 + yv.z) + sb1[4 * q + 2]);
    float h3 = tanhf(dinv * (a3 + yv.w) + sb1[4 * q + 3]);

    float o0, o1, o2, o3;
    {
        const float* w0 = &sW2[(4 * q + 0) * F2];
        const float* w1 = &sW2[(4 * q + 1) * F2];
        const float* w2 = &sW2[(4 * q + 2) * F2];
        const float* w3 = &sW2[(4 * q + 3) * F2];
        o0 = fmaf(h0, w0[0], fmaf(h1, w1[0], fmaf(h2, w2[0], h3 * w3[0])));
        o1 = fmaf(h0, w0[1], fmaf(h1, w1[1], fmaf(h2, w2[1], h3 * w3[1])));
        o2 = fmaf(h0, w0[2], fmaf(h1, w1[2], fmaf(h2, w2[2], h3 * w3[2])));
        o3 = fmaf(h0, w0[3], fmaf(h1, w1[3], fmaf(h2, w2[3], h3 * w3[3])));
    }
    // reduce partials across the 4 quarter-lanes
    o0 += __shfl_down_sync(FULL, o0, 2, 4);
    o1 += __shfl_down_sync(FULL, o1, 2, 4);
    o2 += __shfl_down_sync(FULL, o2, 2, 4);
    o3 += __shfl_down_sync(FULL, o3, 2, 4);
    o0 += __shfl_down_sync(FULL, o0, 1, 4);
    o1 += __shfl_down_sync(FULL, o1, 1, 4);
    o2 += __shfl_down_sync(FULL, o2, 1, 4);
    o3 += __shfl_down_sync(FULL, o3, 1, 4);

    if (j == 0)
        *reinterpret_cast<float4*>(g_y2 + n * F2) =
            make_float4(o0 * dinv, o1 * dinv, o2 * dinv, o3 * dinv);
}

// ---------------- K5: pull layer-2 + fused + @W3 ---------------------------
__global__ void k_pull2(const float* __restrict__ b2, const float* __restrict__ W3) {
    __shared__ float sW3[F2 * F3];
    __shared__ float sb2[F2];
    for (int i = threadIdx.x; i < F2 * F3; i += blockDim.x) sW3[i] = W3[i];
    for (int i = threadIdx.x; i < F2; i += blockDim.x) sb2[i] = b2[i];
    __syncthreads();

    int t = blockIdx.x * blockDim.x + threadIdx.x;
    int n = t >> 2;
    int j = t & 3;
    if (n >= N_NODES) return;

    int2 nfo = g_nfo[n];
    int off = nfo.x, cnt = nfo.y;
    float a0 = 0.0f, a1 = 0.0f, a2 = 0.0f, a3 = 0.0f;
    for (int i = off + j; i < off + cnt; i += 4) {
        int src = __ldg(&g_csr[i]);
        float4 v = *reinterpret_cast<const float4*>(g_y2 + src * F2);
        a0 += v.x; a1 += v.y; a2 += v.z; a3 += v.w;
    }
#pragma unroll
    for (int d = 2; d >= 1; d >>= 1) {
        a0 += __shfl_down_sync(FULL, a0, d, 4);
        a1 += __shfl_down_sync(FULL, a1, d, 4);
        a2 += __shfl_down_sync(FULL, a2, d, 4);
        a3 += __shfl_down_sync(FULL, a3, d, 4);
    }
    if (j == 0) {
        float dinv = g_dinv[n];
        float4 yv = *reinterpret_cast<const float4*>(g_y2 + n * F2);
        float h0 = tanhf(dinv * (a0 + yv.x) + sb2[0]);
        float h1 = tanhf(dinv * (a1 + yv.y) + sb2[1]);
        float h2 = tanhf(dinv * (a2 + yv.z) + sb2[2]);
        float h3 = tanhf(dinv * (a3 + yv.w) + sb2[3]);
        float o0 = fmaf(h0, sW3[0], fmaf(h1, sW3[2], fmaf(h2, sW3[4], h3 * sW3[6])));
        float o1 = fmaf(h0, sW3[1], fmaf(h1, sW3[3], fmaf(h2, sW3[5], h3 * sW3[7])));
        g_y3[n] = make_float2(o0 * dinv, o1 * dinv);
    }
}

// ---------------- K6: pull layer-3 + fused + classifier --------------------
// d_out layout: out[100000,8] then h3[100000,2].
__global__ void k_pull3(const float* __restrict__ b3, const float* __restrict__ Wc,
                        const float* __restrict__ bc, float* __restrict__ out) {
    __shared__ float sWc[F3 * NC];
    __shared__ float sbc[NC];
    __shared__ float sb3[F3];
    for (int i = threadIdx.x; i < F3 * NC; i += blockDim.x) sWc[i] = Wc[i];
    for (int i = threadIdx.x; i < NC; i += blockDim.x) sbc[i] = bc[i];
    for (int i = threadIdx.x; i < F3; i += blockDim.x) sb3[i] = b3[i];
    __syncthreads();

    int t = blockIdx.x * blockDim.x + threadIdx.x;
    int n = t >> 2;
    int j = t & 3;
    if (n >= N_NODES) return;

    int2 nfo = g_nfo[n];
    int off = nfo.x, cnt = nfo.y;
    float a0 = 0.0f, a1 = 0.0f;
    for (int i = off + j; i < off + cnt; i += 4) {
        int src = __ldg(&g_csr[i]);
        float2 v = g_y3[src];
        a0 += v.x; a1 += v.y;
    }
#pragma unroll
    for (int d = 2; d >= 1; d >>= 1) {
        a0 += __shfl_down_sync(FULL, a0, d, 4);
        a1 += __shfl_down_sync(FULL, a1, d, 4);
    }
    if (j == 0) {
        float dinv = g_dinv[n];
        float2 yv = g_y3[n];
        float h3x = tanhf(dinv * (a0 + yv.x) + sb3[0]);
        float h3y = tanhf(dinv * (a1 + yv.y) + sb3[1]);

        float o[NC];
#pragma unroll
        for (int k = 0; k < NC; k++)
            o[k] = fmaf(h3x, sWc[k], fmaf(h3y, sWc[NC + k], sbc[k]));

        float4* op = reinterpret_cast<float4*>(out + (size_t)n * NC);
        op[0] = make_float4(o[0], o[1], o[2], o[3]);
        op[1] = make_float4(o[4], o[5], o[6], o[7]);
        *reinterpret_cast<float2*>(out + (size_t)N_NODES * NC + (size_t)n * F3) =
            make_float2(h3x, h3y);
    }
}

// ---------------- host ------------------------------------------------------
extern "C" void kernel_launch(void* const* d_in, const int* in_sizes, int n_in,
                              void* d_out, int out_size) {
    const float* h  = (const float*)d_in[0];
    const void*  ei = d_in[1];
    const float* W1 = (const float*)d_in[2];
    const float* b1 = (const float*)d_in[3];
    const float* W2 = (const float*)d_in[4];
    const float* b2 = (const float*)d_in[5];
    const float* W3 = (const float*)d_in[6];
    const float* b3 = (const float*)d_in[7];
    const float* Wc = (const float*)d_in[8];
    const float* bc = (const float*)d_in[9];
    float* out = (float*)d_out;

    const int T = 256;
    k_init  <<<400, T>>>((const unsigned int*)ei);
    k_edges <<<(N_EDGES + T - 1) / T, T>>>(ei);
    k_xw1off<<<(N_NODES + T - 1) / T, T>>>(h, W1);
    k_csr   <<<(N_EDGES / 4 + T - 1) / T, T>>>();
    k_pull1 <<<(N_NODES * 8) / T, T>>>(b1, W2);
    k_pull2 <<<(N_NODES * 4 + T - 1) / T, T>>>(b2, W3);
    k_pull3 <<<(N_NODES * 4 + T - 1) / T, T>>>(b3, Wc, bc, out);
}

// round 5
// speedup vs baseline: 1.5972x; 1.1262x over previous
#include <cuda_runtime.h>

#define N_NODES 100000
#define N_EDGES 3200000
#define NFEAT   128
#define F1      16
#define F2      4
#define F3      2
#define NC      8
#define CAP     128          // padded CSR row capacity (deg ~ Poisson(32))
#define OVFCAP  8192
#define FULL    0xffffffffu

// ---------------- scratch (device globals; no allocation allowed) ----------
__device__ int g_is64;
__device__ int g_ovf_cnt;
__device__ __align__(16) int    g_cnt[N_NODES];
__device__ __align__(16) float  g_dinv[N_NODES];
__device__ __align__(16) int    g_pcsr[N_NODES * CAP];   // padded CSR: src ids
__device__ __align__(16) int2   g_ovf[OVFCAP];           // (dst, src) overflow
__device__ __align__(16) float  g_y1[N_NODES * F1];      // (h@W1)*dinv
__device__ __align__(16) float  g_y2[N_NODES * F2];      // xw2*dinv
__device__ __align__(16) float2 g_y3[N_NODES];           // xw3*dinv

// ---------------- K0: detect int64 vs int32 + zero counters ----------------
__global__ void k_init(const unsigned int* __restrict__ w) {
    int i = blockIdx.x * blockDim.x + threadIdx.x;
    int stride = gridDim.x * blockDim.x;
    for (int j = i; j < N_NODES; j += stride) g_cnt[j] = 0;
    if (i == 0) g_ovf_cnt = 0;
    if (blockIdx.x == 0) {
        __shared__ unsigned int s;
        if (threadIdx.x == 0) s = 0u;
        __syncthreads();
        unsigned int nz = 0;
        for (int k = threadIdx.x; k < 2048; k += blockDim.x) nz |= w[2 * k + 1];
        atomicOr(&s, nz);
        __syncthreads();
        if (threadIdx.x == 0) g_is64 = (s == 0u) ? 1 : 0;
    }
}

// ---------------- K1: one-pass padded-CSR build -----------------------------
// rank = atomicAdd return; slot = dst*CAP + rank. No offsets, no scan, no copy.
__global__ void k_edges(const void* __restrict__ ei) {
    int e = blockIdx.x * blockDim.x + threadIdx.x;
    if (e >= N_EDGES) return;
    int s, d;
    if (g_is64) {
        const long long* p = (const long long*)ei;
        s = (int)p[e];
        d = (int)p[N_EDGES + e];
    } else {
        const int* p = (const int*)ei;
        s = p[e];
        d = p[N_EDGES + e];
    }
    int r = atomicAdd(&g_cnt[d], 1);
    if (r < CAP) {
        g_pcsr[d * CAP + r] = s;
    } else {
        int p = atomicAdd(&g_ovf_cnt, 1);
        if (p < OVFCAP) g_ovf[p] = make_int2(d, s);
    }
}

// ---------------- K2: dinv + y1 = (h @ W1) * dinv ---------------------------
__global__ void k_xw1(const float* __restrict__ h, const float* __restrict__ W1) {
    __shared__ float sW[NFEAT * F1];   // 8 KB
    for (int i = threadIdx.x; i < NFEAT * F1; i += blockDim.x) sW[i] = W1[i];
    __syncthreads();

    int n = blockIdx.x * blockDim.x + threadIdx.x;
    if (n >= N_NODES) return;

    int cnt = g_cnt[n];
    float dinv = rsqrtf((float)(cnt + 1));
    g_dinv[n] = dinv;

    float acc[F1];
#pragma unroll
    for (int f = 0; f < F1; f++) acc[f] = 0.0f;

    const float4* h4 = reinterpret_cast<const float4*>(h + (size_t)n * NFEAT);
#pragma unroll 4
    for (int k4 = 0; k4 < NFEAT / 4; k4++) {
        float4 hv = h4[k4];
        const float* w = &sW[(k4 * 4) * F1];
#pragma unroll
        for (int f = 0; f < F1; f++) {
            float a = acc[f];
            a = fmaf(hv.x, w[f],          a);
            a = fmaf(hv.y, w[F1 + f],     a);
            a = fmaf(hv.z, w[2 * F1 + f], a);
            a = fmaf(hv.w, w[3 * F1 + f], a);
            acc[f] = a;
        }
    }
    float4* o = reinterpret_cast<float4*>(g_y1 + n * F1);
#pragma unroll
    for (int q = 0; q < F1 / 4; q++)
        o[q] = make_float4(acc[4 * q] * dinv, acc[4 * q + 1] * dinv,
                           acc[4 * q + 2] * dinv, acc[4 * q + 3] * dinv);
}

// ---------------- K3: pull layer-1 + fused (tanh) + @W2 --------------------
// 8 lanes per node = 2 edge-slots x 4 feature-quarters.
__global__ void k_pull1(const float* __restrict__ b1, const float* __restrict__ W2) {
    __shared__ float sW2[F1 * F2];
    __shared__ float sb1[F1];
    for (int i = threadIdx.x; i < F1 * F2; i += blockDim.x) sW2[i] = W2[i];
    for (int i = threadIdx.x; i < F1; i += blockDim.x) sb1[i] = b1[i];
    __syncthreads();

    int t = blockIdx.x * blockDim.x + threadIdx.x;   // exactly 800000 threads
    int n = t >> 3;
    int j = t & 7;
    int s = j >> 2;       // edge slot 0/1
    int q = j & 3;        // feature quarter

    int cnt = g_cnt[n];
    int lim = min(cnt, CAP);
    int off = n * CAP;

    float a0 = 0.0f, a1 = 0.0f, a2 = 0.0f, a3 = 0.0f;
    for (int i = s; i < lim; i += 2) {
        int src = __ldg(&g_pcsr[off + i]);
        float4 v = *reinterpret_cast<const float4*>(g_y1 + src * F1 + q * 4);
        a0 += v.x; a1 += v.y; a2 += v.z; a3 += v.w;
    }
    int oc = g_ovf_cnt;                 // 0 in practice
    if (oc > 0) {
        if (oc > OVFCAP) oc = OVFCAP;
        for (int i = s; i < oc; i += 2) {
            int2 e = g_ovf[i];
            if (e.x == n) {
                float4 v = *reinterpret_cast<const float4*>(g_y1 + e.y * F1 + q * 4);
                a0 += v.x; a1 += v.y; a2 += v.z; a3 += v.w;
            }
        }
    }
    // combine the two edge slots (width-8 groups)
    a0 += __shfl_down_sync(FULL, a0, 4, 8);
    a1 += __shfl_down_sync(FULL, a1, 4, 8);
    a2 += __shfl_down_sync(FULL, a2, 4, 8);
    a3 += __shfl_down_sync(FULL, a3, 4, 8);

    // lanes j=0..3 hold quarter q=j sums; partial epilogue on each
    float dinv = g_dinv[n];
    float4 yv = *reinterpret_cast<const float4*>(g_y1 + n * F1 + q * 4);
    float h0 = tanhf(dinv * (a0 + yv.x) + sb1[4 * q + 0]);
    float h1 = tanhf(dinv * (a1 + yv.y) + sb1[4 * q + 1]);
    float h2 = tanhf(dinv * (a2 + yv.z) + sb1[4 * q + 2]);
    float h3 = tanhf(dinv * (a3 + yv.w) + sb1[4 * q + 3]);

    float o0, o1, o2, o3;
    {
        const float* w0 = &sW2[(4 * q + 0) * F2];
        const float* w1 = &sW2[(4 * q + 1) * F2];
        const float* w2 = &sW2[(4 * q + 2) * F2];
        const float* w3 = &sW2[(4 * q + 3) * F2];
        o0 = fmaf(h0, w0[0], fmaf(h1, w1[0], fmaf(h2, w2[0], h3 * w3[0])));
        o1 = fmaf(h0, w0[1], fmaf(h1, w1[1], fmaf(h2, w2[1], h3 * w3[1])));
        o2 = fmaf(h0, w0[2], fmaf(h1, w1[2], fmaf(h2, w2[2], h3 * w3[2])));
        o3 = fmaf(h0, w0[3], fmaf(h1, w1[3], fmaf(h2, w2[3], h3 * w3[3])));
    }
    // reduce partials across the 4 quarter-lanes
    o0 += __shfl_down_sync(FULL, o0, 2, 4);
    o1 += __shfl_down_sync(FULL, o1, 2, 4);
    o2 += __shfl_down_sync(FULL, o2, 2, 4);
    o3 += __shfl_down_sync(FULL, o3, 2, 4);
    o0 += __shfl_down_sync(FULL, o0, 1, 4);
    o1 += __shfl_down_sync(FULL, o1, 1, 4);
    o2 += __shfl_down_sync(FULL, o2, 1, 4);
    o3 += __shfl_down_sync(FULL, o3, 1, 4);

    if (j == 0)
        *reinterpret_cast<float4*>(g_y2 + n * F2) =
            make_float4(o0 * dinv, o1 * dinv, o2 * dinv, o3 * dinv);
}

// ---------------- K4: pull layer-2 + fused + @W3 ---------------------------
__global__ void k_pull2(const float* __restrict__ b2, const float* __restrict__ W3) {
    __shared__ float sW3[F2 * F3];
    __shared__ float sb2[F2];
    for (int i = threadIdx.x; i < F2 * F3; i += blockDim.x) sW3[i] = W3[i];
    for (int i = threadIdx.x; i < F2; i += blockDim.x) sb2[i] = b2[i];
    __syncthreads();

    int t = blockIdx.x * blockDim.x + threadIdx.x;
    int n = t >> 2;
    int j = t & 3;
    if (n >= N_NODES) return;

    int cnt = g_cnt[n];
    int lim = min(cnt, CAP);
    int off = n * CAP;
    float a0 = 0.0f, a1 = 0.0f, a2 = 0.0f, a3 = 0.0f;
    for (int i = j; i < lim; i += 4) {
        int src = __ldg(&g_pcsr[off + i]);
        float4 v = *reinterpret_cast<const float4*>(g_y2 + src * F2);
        a0 += v.x; a1 += v.y; a2 += v.z; a3 += v.w;
    }
    int oc = g_ovf_cnt;
    if (oc > 0) {
        if (oc > OVFCAP) oc = OVFCAP;
        for (int i = j; i < oc; i += 4) {
            int2 e = g_ovf[i];
            if (e.x == n) {
                float4 v = *reinterpret_cast<const float4*>(g_y2 + e.y * F2);
                a0 += v.x; a1 += v.y; a2 += v.z; a3 += v.w;
            }
        }
    }
#pragma unroll
    for (int d = 2; d >= 1; d >>= 1) {
        a0 += __shfl_down_sync(FULL, a0, d, 4);
        a1 += __shfl_down_sync(FULL, a1, d, 4);
        a2 += __shfl_down_sync(FULL, a2, d, 4);
        a3 += __shfl_down_sync(FULL, a3, d, 4);
    }
    if (j == 0) {
        float dinv = g_dinv[n];
        float4 yv = *reinterpret_cast<const float4*>(g_y2 + n * F2);
        float h0 = tanhf(dinv * (a0 + yv.x) + sb2[0]);
        float h1 = tanhf(dinv * (a1 + yv.y) + sb2[1]);
        float h2 = tanhf(dinv * (a2 + yv.z) + sb2[2]);
        float h3 = tanhf(dinv * (a3 + yv.w) + sb2[3]);
        float o0 = fmaf(h0, sW3[0], fmaf(h1, sW3[2], fmaf(h2, sW3[4], h3 * sW3[6])));
        float o1 = fmaf(h0, sW3[1], fmaf(h1, sW3[3], fmaf(h2, sW3[5], h3 * sW3[7])));
        g_y3[n] = make_float2(o0 * dinv, o1 * dinv);
    }
}

// ---------------- K5: pull layer-3 + fused + classifier --------------------
// d_out layout: out[100000,8] then h3[100000,2].
__global__ void k_pull3(const float* __restrict__ b3, const float* __restrict__ Wc,
                        const float* __restrict__ bc, float* __restrict__ out) {
    __shared__ float sWc[F3 * NC];
    __shared__ float sbc[NC];
    __shared__ float sb3[F3];
    for (int i = threadIdx.x; i < F3 * NC; i += blockDim.x) sWc[i] = Wc[i];
    for (int i = threadIdx.x; i < NC; i += blockDim.x) sbc[i] = bc[i];
    for (int i = threadIdx.x; i < F3; i += blockDim.x) sb3[i] = b3[i];
    __syncthreads();

    int t = blockIdx.x * blockDim.x + threadIdx.x;
    int n = t >> 2;
    int j = t & 3;
    if (n >= N_NODES) return;

    int cnt = g_cnt[n];
    int lim = min(cnt, CAP);
    int off = n * CAP;
    float a0 = 0.0f, a1 = 0.0f;
    for (int i = j; i < lim; i += 4) {
        int src = __ldg(&g_pcsr[off + i]);
        float2 v = g_y3[src];
        a0 += v.x; a1 += v.y;
    }
    int oc = g_ovf_cnt;
    if (oc > 0) {
        if (oc > OVFCAP) oc = OVFCAP;
        for (int i = j; i < oc; i += 4) {
            int2 e = g_ovf[i];
            if (e.x == n) {
                float2 v = g_y3[e.y];
                a0 += v.x; a1 += v.y;
            }
        }
    }
#pragma unroll
    for (int d = 2; d >= 1; d >>= 1) {
        a0 += __shfl_down_sync(FULL, a0, d, 4);
        a1 += __shfl_down_sync(FULL, a1, d, 4);
    }
    if (j == 0) {
        float dinv = g_dinv[n];
        float2 yv = g_y3[n];
        float h3x = tanhf(dinv * (a0 + yv.x) + sb3[0]);
        float h3y = tanhf(dinv * (a1 + yv.y) + sb3[1]);

        float o[NC];
#pragma unroll
        for (int k = 0; k < NC; k++)
            o[k] = fmaf(h3x, sWc[k], fmaf(h3y, sWc[NC + k], sbc[k]));

        float4* op = reinterpret_cast<float4*>(out + (size_t)n * NC);
        op[0] = make_float4(o[0], o[1], o[2], o[3]);
        op[1] = make_float4(o[4], o[5], o[6], o[7]);
        *reinterpret_cast<float2*>(out + (size_t)N_NODES * NC + (size_t)n * F3) =
            make_float2(h3x, h3y);
    }
}

// ---------------- host ------------------------------------------------------
extern "C" void kernel_launch(void* const* d_in, const int* in_sizes, int n_in,
                              void* d_out, int out_size) {
    const float* h  = (const float*)d_in[0];
    const void*  ei = d_in[1];
    const float* W1 = (const float*)d_in[2];
    const float* b1 = (const float*)d_in[3];
    const float* W2 = (const float*)d_in[4];
    const float* b2 = (const float*)d_in[5];
    const float* W3 = (const float*)d_in[6];
    const float* b3 = (const float*)d_in[7];
    const float* Wc = (const float*)d_in[8];
    const float* bc = (const float*)d_in[9];
    float* out = (float*)d_out;

    const int T = 256;
    k_init <<<400, T>>>((const unsigned int*)ei);
    k_edges<<<(N_EDGES + T - 1) / T, T>>>(ei);
    k_xw1  <<<(N_NODES + T - 1) / T, T>>>(h, W1);
    k_pull1<<<(N_NODES * 8) / T, T>>>(b1, W2);
    k_pull2<<<(N_NODES * 4 + T - 1) / T, T>>>(b2, W3);
    k_pull3<<<(N_NODES * 4 + T - 1) / T, T>>>(b3, Wc, bc, out);
}